// round 14
// baseline (speedup 1.0000x reference)
#include <cuda_runtime.h>
#include <cuda_bf16.h>
#include <math_constants.h>

// Problem constants (fixed shapes)
#define B_   8
#define C_   21
#define H_   512
#define W_   512
#define HW_  (H_ * W_)           // 262144 = 2^18
#define HW_SHIFT 18
#define NPIX (B_ * HW_)          // 2097152
#define MAX_M 0.5f
#define S_    30.0f

#define HGRID (NPIX / 4 / 256)   // 2048 blocks: one int4 per thread
#define LGRID (NPIX / 256)       // 8192 blocks: one pixel per thread (R3)

// Scratch (device globals — no allocations allowed). All overwritten every
// launch in graph order, so replays are deterministic.
__device__ int    g_parts[HGRID][C_];   // per-block histogram partials
__device__ float  g_mlist[C_];
__device__ double g_loss;

// ---------------------------------------------------------------------------
// Kernel 1: per-block label histograms, one int4/thread.
//  - __match_any_sync aggregation: for each of the 4 labels, lanes holding the
//    same class elect one leader which performs a single conflict-free smem
//    atomic with the popc'd count -> no ATOMS multiplicity replays.
//  - Partials written with plain stores (no same-address global atomics);
//    the kernel boundary orders them before mlist reads them.
//  - Block 0 zeroes g_loss (consumed only by the strictly-later loss kernel).
// ---------------------------------------------------------------------------
__global__ __launch_bounds__(256) void hist_kernel(const int* __restrict__ target) {
    __shared__ int sh[8][C_];
    const int tid  = threadIdx.x;
    const int wid  = tid >> 5;
    const int lane = tid & 31;

    for (int i = tid; i < 8 * C_; i += 256) (&sh[0][0])[i] = 0;
    if (blockIdx.x == 0 && tid == 0) g_loss = 0.0;
    __syncthreads();

    int4 v = __ldg(reinterpret_cast<const int4*>(target) + blockIdx.x * 256 + tid);

#define ACC_LABEL(val)                                                        \
    do {                                                                      \
        unsigned mk = __match_any_sync(0xffffffffu, (val));                   \
        if (lane == __ffs(mk) - 1)                                            \
            atomicAdd(&sh[wid][(val)], __popc(mk));                           \
    } while (0)

    ACC_LABEL(v.x);
    ACC_LABEL(v.y);
    ACC_LABEL(v.z);
    ACC_LABEL(v.w);
#undef ACC_LABEL
    __syncthreads();

    if (tid < C_) {
        int s = 0;
#pragma unroll
        for (int w = 0; w < 8; w++) s += sh[w][tid];
        g_parts[blockIdx.x][tid] = s;           // plain store, no atomic
    }
}

// ---------------------------------------------------------------------------
// Kernel 2: reduce partials -> counts -> m_list (21 warps; warp w owns class w)
// ---------------------------------------------------------------------------
__global__ void mlist_kernel() {
    __shared__ float cnt[C_];
    const int w    = threadIdx.x >> 5;   // 0..20
    const int lane = threadIdx.x & 31;

    int s = 0;
#pragma unroll 4
    for (int p = lane; p < HGRID; p += 32) s += g_parts[p][w];
#pragma unroll
    for (int o = 16; o > 0; o >>= 1) s += __shfl_xor_sync(0xffffffffu, s, o);
    if (lane == 0) cnt[w] = (float)s;
    __syncthreads();

    if (w == 0) {
        float mi = 0.0f, m = -CUDART_INF_F;
        if (lane < C_) {
            mi = rsqrtf(sqrtf(cnt[lane] + 1e-4f));
            m  = mi;
        }
#pragma unroll
        for (int o = 16; o > 0; o >>= 1)
            m = fmaxf(m, __shfl_xor_sync(0xffffffffu, m, o));
        if (lane < C_) g_mlist[lane] = mi * (MAX_M / m);
    }
}

// ---------------------------------------------------------------------------
// Kernel 3: LDAM NLL — the literal R3 optimum (33.1us, DRAM 71.7%, occ 91.4%):
// 1 pixel/thread, single pass, in-loop margin, static indexing so v[] stays
// in registers, per-block f64 atomic. NO fences / done-counters (they cost
// ~3us of tail in R13).
// ---------------------------------------------------------------------------
__global__ __launch_bounds__(256) void loss_kernel(const float* __restrict__ pred,
                                                   const int*   __restrict__ target) {
    int n  = blockIdx.x * 256 + threadIdx.x;   // exact grid: n < NPIX
    int b  = n >> HW_SHIFT;
    int hw = n & (HW_ - 1);
    const float* base = pred + (size_t)(b * C_) * HW_ + hw;

    int   l = target[n];
    float m = g_mlist[l];

    float v[C_];
    float maxv = -CUDART_INF_F;
    float vl   = 0.0f;
#pragma unroll
    for (int c = 0; c < C_; c++) {
        float x = __ldg(base + (size_t)c * HW_);
        if (c == l) x -= m;
        v[c] = x;
        maxv = fmaxf(maxv, x);
        if (c == l) vl = x;
    }

    float s = 0.0f;
#pragma unroll
    for (int c = 0; c < C_; c++)
        s += __expf(S_ * (v[c] - maxv));

    float nll = __logf(s) + S_ * (maxv - vl);

#pragma unroll
    for (int o = 16; o > 0; o >>= 1)
        nll += __shfl_xor_sync(0xffffffffu, nll, o);

    __shared__ float warp_sums[8];
    int lane = threadIdx.x & 31;
    int wid  = threadIdx.x >> 5;
    if (lane == 0) warp_sums[wid] = nll;
    __syncthreads();

    if (wid == 0) {
        float x = (lane < 8) ? warp_sums[lane] : 0.0f;
#pragma unroll
        for (int o = 4; o > 0; o >>= 1)
            x += __shfl_xor_sync(0xffffffffu, x, o);
        if (lane == 0) atomicAdd(&g_loss, (double)x);
    }
}

// ---------------------------------------------------------------------------
// Kernel 4: finalize — mean, write f32 scalar (tiny kernels cost <1us in-graph)
// ---------------------------------------------------------------------------
__global__ void finalize_kernel(float* __restrict__ out) {
    out[0] = (float)(g_loss * (1.0 / (double)NPIX));
}

// ---------------------------------------------------------------------------
extern "C" void kernel_launch(void* const* d_in, const int* in_sizes, int n_in,
                              void* d_out, int out_size) {
    const float* pred   = (const float*)d_in[0];
    const int*   target = (const int*)d_in[1];
    float*       out    = (float*)d_out;

    hist_kernel<<<HGRID, 256>>>(target);
    mlist_kernel<<<1, C_ * 32>>>();
    loss_kernel<<<LGRID, 256>>>(pred, target);
    finalize_kernel<<<1, 1>>>(out);
}

// round 15
// speedup vs baseline: 1.1291x; 1.1291x over previous
#include <cuda_runtime.h>
#include <cuda_bf16.h>
#include <math_constants.h>

// Problem constants (fixed shapes)
#define B_   8
#define C_   21
#define H_   512
#define W_   512
#define HW_  (H_ * W_)           // 262144 = 2^18
#define HW_SHIFT 18
#define NPIX (B_ * HW_)          // 2097152
#define MAX_M 0.5f
#define S_    30.0f

#define K_    43.2808512266689f  // S * log2(e): exp(S*x) == exp2(K*x)
#define LN2_  0.6931471805599453f

#define HGRID 512                // 512 blk * 256 thr * 16 labels = NPIX
#define LGRID (NPIX / 256)       // 8192 blocks, 1 pixel/thread (proven R3)

// Scratch (device globals). Overwritten in graph order every launch.
__device__ int    g_parts[C_][HGRID];  // TRANSPOSED: mlist reads coalesced
__device__ float  g_mlist[C_];
__device__ double g_loss;

// ---------------------------------------------------------------------------
// Kernel 1: per-block label histograms. 4 batched int4 loads (MLP=4);
// __match_any_sync aggregation (one conflict-free smem atomic per distinct
// class per warp -> no ATOMS multiplicity replays); transposed plain-store
// partials. Block 0 zeroes g_loss (read only by the strictly-later loss).
// ---------------------------------------------------------------------------
__global__ __launch_bounds__(256) void hist_kernel(const int* __restrict__ target) {
    __shared__ int sh[8][C_];
    const int tid  = threadIdx.x;
    const int wid  = tid >> 5;
    const int lane = tid & 31;

    for (int i = tid; i < 8 * C_; i += 256) (&sh[0][0])[i] = 0;
    if (blockIdx.x == 0 && tid == 0) g_loss = 0.0;
    __syncthreads();

    const int4* t4 = reinterpret_cast<const int4*>(target);
    int4 a[4];
#pragma unroll
    for (int k = 0; k < 4; k++)
        a[k] = __ldg(t4 + blockIdx.x * 1024 + k * 256 + tid);

#define ACC_LABEL(val)                                                        \
    do {                                                                      \
        unsigned mk = __match_any_sync(0xffffffffu, (val));                   \
        if (lane == __ffs(mk) - 1)                                            \
            atomicAdd(&sh[wid][(val)], __popc(mk));                           \
    } while (0)

#pragma unroll
    for (int k = 0; k < 4; k++) {
        ACC_LABEL(a[k].x);
        ACC_LABEL(a[k].y);
        ACC_LABEL(a[k].z);
        ACC_LABEL(a[k].w);
    }
#undef ACC_LABEL
    __syncthreads();

    if (tid < C_) {
        int s = 0;
#pragma unroll
        for (int w = 0; w < 8; w++) s += sh[w][tid];
        g_parts[tid][blockIdx.x] = s;          // transposed, plain store
    }
}

// ---------------------------------------------------------------------------
// Kernel 2: partials -> counts -> m_list. Warp w owns class w; its lanes read
// g_parts[w][lane + 32k] -> fully coalesced 128B lines, 16 independent loads
// fully unrolled (all in flight at once).
// ---------------------------------------------------------------------------
__global__ void mlist_kernel() {
    __shared__ float cnt[C_];
    const int w    = threadIdx.x >> 5;   // 0..20
    const int lane = threadIdx.x & 31;

    int s = 0;
#pragma unroll
    for (int k = 0; k < HGRID / 32; k++)     // 16 coalesced, independent
        s += g_parts[w][k * 32 + lane];
#pragma unroll
    for (int o = 16; o > 0; o >>= 1) s += __shfl_xor_sync(0xffffffffu, s, o);
    if (lane == 0) cnt[w] = (float)s;
    __syncthreads();

    if (w == 0) {
        float mi = 0.0f, m = -CUDART_INF_F;
        if (lane < C_) {
            mi = rsqrtf(sqrtf(cnt[lane] + 1e-4f));
            m  = mi;
        }
#pragma unroll
        for (int o = 16; o > 0; o >>= 1)
            m = fmaxf(m, __shfl_xor_sync(0xffffffffu, m, o));
        if (lane < C_) g_mlist[lane] = mi * (MAX_M / m);
    }
}

// ---------------------------------------------------------------------------
// Kernel 3: LDAM NLL — the R3 optimum body (1 pixel/thread, single pass,
// in-loop margin, static indexing keeps v[] in registers, per-block f64
// atomic, no fences/counters). Single micro-opt: exp(S*x) computed as
// exp2(K*x) with K = S*log2(e), so each channel is exactly FFMA + MUFU.EX2
// (removes the per-channel FMUL by log2e). log(s) = lg2(s)*ln2.
// ---------------------------------------------------------------------------
__global__ __launch_bounds__(256) void loss_kernel(const float* __restrict__ pred,
                                                   const int*   __restrict__ target) {
    int n  = blockIdx.x * 256 + threadIdx.x;   // exact grid: n < NPIX
    int b  = n >> HW_SHIFT;
    int hw = n & (HW_ - 1);
    const float* base = pred + (size_t)(b * C_) * HW_ + hw;

    int   l = target[n];
    float m = g_mlist[l];

    float v[C_];
    float maxv = -CUDART_INF_F;
    float vl   = 0.0f;
#pragma unroll
    for (int c = 0; c < C_; c++) {
        float x = __ldg(base + (size_t)c * HW_);
        if (c == l) x -= m;
        v[c] = x;
        maxv = fmaxf(maxv, x);
        if (c == l) vl = x;
    }

    float km = K_ * maxv;
    float s  = 0.0f;
#pragma unroll
    for (int c = 0; c < C_; c++)
        s += exp2f(fmaf(K_, v[c], -km));       // FFMA + MUFU.EX2

    float nll = LN2_ * __log2f(s) + S_ * (maxv - vl);

#pragma unroll
    for (int o = 16; o > 0; o >>= 1)
        nll += __shfl_xor_sync(0xffffffffu, nll, o);

    __shared__ float warp_sums[8];
    int lane = threadIdx.x & 31;
    int wid  = threadIdx.x >> 5;
    if (lane == 0) warp_sums[wid] = nll;
    __syncthreads();

    if (wid == 0) {
        float x = (lane < 8) ? warp_sums[lane] : 0.0f;
#pragma unroll
        for (int o = 4; o > 0; o >>= 1)
            x += __shfl_xor_sync(0xffffffffu, x, o);
        if (lane == 0) atomicAdd(&g_loss, (double)x);
    }
}

// ---------------------------------------------------------------------------
// Kernel 4: finalize — mean, write f32 scalar
// ---------------------------------------------------------------------------
__global__ void finalize_kernel(float* __restrict__ out) {
    out[0] = (float)(g_loss * (1.0 / (double)NPIX));
}

// ---------------------------------------------------------------------------
extern "C" void kernel_launch(void* const* d_in, const int* in_sizes, int n_in,
                              void* d_out, int out_size) {
    const float* pred   = (const float*)d_in[0];
    const int*   target = (const int*)d_in[1];
    float*       out    = (float*)d_out;

    hist_kernel<<<HGRID, 256>>>(target);
    mlist_kernel<<<1, C_ * 32>>>();
    loss_kernel<<<LGRID, 256>>>(pred, target);
    finalize_kernel<<<1, 1>>>(out);
}